// round 12
// baseline (speedup 1.0000x reference)
#include <cuda_runtime.h>
#include <cuda_bf16.h>
#include <cstdint>

// ============================================================================
// FullGap: out[s] = sum_{i in s} (p_i^T M p_i)/(p_i.p_i),
//          M = sum_j w[colseg[j]] s_j s_j^T  (256x256 symmetric)
// x^T M x = 2 x^T U x,  U = strict-upper(M) + diag(M)/2.
// R12: build v3 FIXED (SFB row stride 256; was 512 overflowing into BAH)
//      -> convM -> quad (R9 proven).
// ============================================================================

#define D_FEAT 256
#define QM 128

__device__ float g_bpart[192][8192];                            // 6 MB partials
__device__ __align__(16) __nv_bfloat16 g_Uhi[D_FEAT * D_FEAT];  // [n][a]
__device__ __align__(16) __nv_bfloat16 g_Ulo[D_FEAT * D_FEAT];

// ---------------- helpers ----------------------------------------------------
__device__ __forceinline__ uint32_t smem_u32(const void* p) {
    uint32_t a;
    asm("{ .reg .u64 t; cvta.to.shared.u64 t, %1; cvt.u32.u64 %0, t; }"
        : "=r"(a) : "l"(p));
    return a;
}
__device__ __forceinline__ uint32_t sw_off(uint32_t off) {
    return off ^ ((off >> 3) & 0x70);
}
__device__ __forceinline__ void cpa16(uint32_t dst, const void* src) {
    asm volatile("cp.async.cg.shared.global [%0], [%1], 16;"
                 :: "r"(dst), "l"(__cvta_generic_to_global(src)) : "memory");
}
#define CP_COMMIT() asm volatile("cp.async.commit_group;" ::: "memory")
#define CP_WAIT(n)  asm volatile("cp.async.wait_group %0;" :: "n"(n) : "memory")

// non-trans A: smem[m][k] (quad)
__device__ __forceinline__ void ldsmA(uint32_t base, int rb, int kk, int lane,
                                      uint32_t* a) {
    int g = lane >> 3, r = lane & 7;
    int row = rb + r + (g & 1) * 8;
    int col = kk + (g >> 1) * 8;
    uint32_t addr = base + sw_off((uint32_t)(row * 128 + col * 2));
    asm volatile("ldmatrix.sync.aligned.m8n8.x4.shared.b16 {%0,%1,%2,%3}, [%4];"
                 : "=r"(a[0]), "=r"(a[1]), "=r"(a[2]), "=r"(a[3]) : "r"(addr));
}
// non-trans B: smem[n][k] (quad)
__device__ __forceinline__ void ldsmB(uint32_t base, int nb, int kk, int lane,
                                      uint32_t* b) {
    int g = lane >> 3, r = lane & 7;
    int row = nb + r + (g >> 1) * 8;
    int col = kk + (g & 1) * 8;
    uint32_t addr = base + sw_off((uint32_t)(row * 128 + col * 2));
    asm volatile("ldmatrix.sync.aligned.m8n8.x4.shared.b16 {%0,%1,%2,%3}, [%4];"
                 : "=r"(b[0]), "=r"(b[1]), "=r"(b[2]), "=r"(b[3]) : "r"(addr));
}
// trans A: smem[j][m], panels of 64 rows x 64 cols (8 KB each)
__device__ __forceinline__ void ldsmT_A(uint32_t base, int ab, int kk, int lane,
                                        uint32_t* a) {
    int g = lane >> 3, r = lane & 7;
    int row = kk + r + (g >> 1) * 8;
    int col = ab + (g & 1) * 8;
    uint32_t addr = base + (uint32_t)(col >> 6) * 8192 +
                    sw_off((uint32_t)(row * 128 + (col & 63) * 2));
    asm volatile("ldmatrix.sync.aligned.m8n8.x4.trans.shared.b16 {%0,%1,%2,%3}, [%4];"
                 : "=r"(a[0]), "=r"(a[1]), "=r"(a[2]), "=r"(a[3]) : "r"(addr));
}
// trans B: smem[j][n], single 64-col panel
__device__ __forceinline__ void ldsmT_B(uint32_t base, int nb, int kk, int lane,
                                        uint32_t* b) {
    int g = lane >> 3, r = lane & 7;
    int row = kk + r + (g & 1) * 8;
    int col = nb + (g >> 1) * 8;
    uint32_t addr = base + sw_off((uint32_t)(row * 128 + col * 2));
    asm volatile("ldmatrix.sync.aligned.m8n8.x4.trans.shared.b16 {%0,%1,%2,%3}, [%4];"
                 : "=r"(b[0]), "=r"(b[1]), "=r"(b[2]), "=r"(b[3]) : "r"(addr));
}
__device__ __forceinline__ void mma16816(float* c, const uint32_t* a,
                                         const uint32_t* b) {
    asm volatile(
        "mma.sync.aligned.m16n8k16.row.col.f32.bf16.bf16.f32 "
        "{%0,%1,%2,%3}, {%4,%5,%6,%7}, {%8,%9}, {%0,%1,%2,%3};"
        : "+f"(c[0]), "+f"(c[1]), "+f"(c[2]), "+f"(c[3])
        : "r"(a[0]), "r"(a[1]), "r"(a[2]), "r"(a[3]), "r"(b[0]), "r"(b[1]));
}
__device__ __forceinline__ void bsplit(float x, float y, uint32_t& hi, uint32_t& lo) {
    float hx = __bfloat162float(__float2bfloat16(x));
    float hy = __bfloat162float(__float2bfloat16(y));
    __nv_bfloat162 h = __floats2bfloat162_rn(hx, hy);
    __nv_bfloat162 l = __floats2bfloat162_rn(x - hx, y - hy);
    hi = *(uint32_t*)&h;
    lo = *(uint32_t*)&l;
}

// ---- build v3: M[a,b] = sum_j S[j][a] * w_j S[j][b] ---------------------------
// 192 CTAs = 6 tiles (128a x 64b, upper coverage) x 32 splits. 256 thr, 2/SM.
#define SFA  0u       // 32768  fp32 A chunk (64j x 128a, row stride 512B)
#define SFB  32768u   // 16384  fp32 B chunk (64j x 64b,  row stride 256B)
#define BAH  49152u   // 16384
#define BAL  65536u   // 16384
#define BBH  81920u   // 8192
#define BBL  90112u   // 8192
#define BWO  98304u   // 1024
#define SMB_TOTAL 99328

__device__ __forceinline__ void b_issue(char* smem, uint32_t sbase,
                                        const float* S, int jb,
                                        int a0, int b0, bool sub,
                                        int n_support, int t) {
#pragma unroll
    for (int p = 0; p < 8; p++) {
        int g = t + p * 256;          // 2048 granules = 64j x 32 float4
        int jl = g >> 5, cq = g & 31;
        int jg = jb + jl;
        uint32_t dst = SFA + (uint32_t)(jl * 512 + cq * 16);
        if (jg < n_support)
            cpa16(sbase + dst, &S[(size_t)jg * D_FEAT + a0 + cq * 4]);
        else
            *(uint4*)(smem + dst) = make_uint4(0, 0, 0, 0);
    }
    if (!sub) {
#pragma unroll
        for (int p = 0; p < 4; p++) {
            int g = t + p * 256;      // 1024 granules = 64j x 16 float4
            int jl = g >> 4, cq = g & 15;
            int jg = jb + jl;
            uint32_t dst = SFB + (uint32_t)(jl * 256 + cq * 16);   // FIXED stride
            if (jg < n_support)
                cpa16(sbase + dst, &S[(size_t)jg * D_FEAT + b0 + cq * 4]);
            else
                *(uint4*)(smem + dst) = make_uint4(0, 0, 0, 0);
        }
    }
}

__global__ void __launch_bounds__(256, 2)
k_build_mma(const float* __restrict__ S, const float* __restrict__ W,
            const int* __restrict__ colseg, int n_support) {
    extern __shared__ char smem[];
    const uint32_t sbase = smem_u32(smem);
    float* wsm = (float*)(smem + BWO);
    const int t    = threadIdx.x;
    const int lane = t & 31;
    const int w    = t >> 5;
    const int wr   = w & 1;        // 2 row groups of 64 rows (a-dim)
    const int wc   = w >> 1;       // 4 col groups of 16 cols (b-dim)

    const int tile  = blockIdx.x >> 5;
    const int split = blockIdx.x & 31;
    const int a0 = (tile < 4) ? 0 : 128;
    const int b0 = (tile < 4) ? tile * 64 : 128 + (tile - 4) * 64;
    const bool sub = (b0 >= a0) && (b0 < a0 + 128);
    const int boff = (b0 - a0) >> 2;     // float4 offset inside A slab
    const int jorg = split * 256;

    {
        int jg = jorg + t;
        wsm[t] = (jg < n_support) ? W[colseg[jg]] : 0.f;
    }

    b_issue(smem, sbase, S, jorg, a0, b0, sub, n_support, t);
    CP_COMMIT();

    float acc[4][2][4];
#pragma unroll
    for (int mt = 0; mt < 4; mt++)
#pragma unroll
        for (int n2 = 0; n2 < 2; n2++)
#pragma unroll
            for (int e = 0; e < 4; e++) acc[mt][n2][e] = 0.f;

#pragma unroll 1
    for (int c = 0; c < 4; c++) {
        CP_WAIT(0);
        __syncthreads();   // loads visible; prev MMA done (bf16 writable)

        // convert A: fp32 -> bf16 hi/lo trans panels
#pragma unroll
        for (int p = 0; p < 8; p++) {
            int g = t + p * 256;
            int jl = g >> 5, cq = g & 31;
            float4 v = *(const float4*)(smem + SFA + jl * 512 + cq * 16);
            uint32_t h0, l0, h1, l1;
            bsplit(v.x, v.y, h0, l0);
            bsplit(v.z, v.w, h1, l1);
            uint32_t off = (uint32_t)(cq >> 4) * 8192 +
                           sw_off((uint32_t)(jl * 128 + (cq & 15) * 8));
            *(uint2*)(smem + BAH + off) = make_uint2(h0, h1);
            *(uint2*)(smem + BAL + off) = make_uint2(l0, l1);
        }
        // convert B: w_j * fp32 -> bf16 hi/lo
#pragma unroll
        for (int p = 0; p < 4; p++) {
            int g = t + p * 256;
            int jl = g >> 4, cq = g & 15;
            uint32_t src = sub ? (SFA + (uint32_t)(jl * 512 + (cq + boff) * 16))
                               : (SFB + (uint32_t)(jl * 256 + cq * 16));  // FIXED
            float4 v = *(const float4*)(smem + src);
            float wj = wsm[c * 64 + jl];
            uint32_t h0, l0, h1, l1;
            bsplit(wj * v.x, wj * v.y, h0, l0);
            bsplit(wj * v.z, wj * v.w, h1, l1);
            uint32_t off = sw_off((uint32_t)(jl * 128 + cq * 8));
            *(uint2*)(smem + BBH + off) = make_uint2(h0, h1);
            *(uint2*)(smem + BBL + off) = make_uint2(l0, l1);
        }
        __syncthreads();   // converts done; fp32 stage free; bf16 ready

        if (c < 3) {       // overlap next chunk's loads with this chunk's MMA
            b_issue(smem, sbase, S, jorg + (c + 1) * 64, a0, b0, sub,
                    n_support, t);
            CP_COMMIT();
        }

#pragma unroll
        for (int ks = 0; ks < 4; ks++) {
            const int kk = ks * 16;
            uint32_t Ah[4][4], Al[4][4], Bh[4], Bl[4];
#pragma unroll
            for (int mt = 0; mt < 4; mt++) {
                ldsmT_A(sbase + BAH, wr * 64 + mt * 16, kk, lane, Ah[mt]);
                ldsmT_A(sbase + BAL, wr * 64 + mt * 16, kk, lane, Al[mt]);
            }
            ldsmT_B(sbase + BBH, wc * 16, kk, lane, Bh);
            ldsmT_B(sbase + BBL, wc * 16, kk, lane, Bl);
#pragma unroll
            for (int mt = 0; mt < 4; mt++)
#pragma unroll
                for (int n2 = 0; n2 < 2; n2++)
                    mma16816(acc[mt][n2], Ah[mt], Bh + n2 * 2);
#pragma unroll
            for (int mt = 0; mt < 4; mt++)
#pragma unroll
                for (int n2 = 0; n2 < 2; n2++)
                    mma16816(acc[mt][n2], Ah[mt], Bl + n2 * 2);
#pragma unroll
            for (int mt = 0; mt < 4; mt++)
#pragma unroll
                for (int n2 = 0; n2 < 2; n2++)
                    mma16816(acc[mt][n2], Al[mt], Bh + n2 * 2);
        }
    }

    // epilogue: stage [b][a] in smem (fp32 stage dead), coalesced store
    __syncthreads();
    float* stg = (float*)smem;
#pragma unroll
    for (int mt = 0; mt < 4; mt++)
#pragma unroll
        for (int n2 = 0; n2 < 2; n2++)
#pragma unroll
            for (int e = 0; e < 4; e++) {
                int a = wr * 64 + mt * 16 + (lane >> 2) + (e >> 1) * 8;
                int b = wc * 16 + n2 * 8 + (lane & 3) * 2 + (e & 1);
                stg[b * 128 + a] = acc[mt][n2][e];
            }
    __syncthreads();
    float* dst = g_bpart[blockIdx.x];
#pragma unroll
    for (int i = 0; i < 32; i++)
        dst[i * 256 + t] = stg[i * 256 + t];
}

// ---- convM: reduce partials -> U bf16 hi/lo, zero out -------------------------
__global__ void k_convM(float* __restrict__ out, int n_struct) {
    int i = blockIdx.x * blockDim.x + threadIdx.x;   // 65536, i = n*256+a
    if (i < n_struct) out[i] = 0.f;
    int a = i & 255, n = i >> 8;
    float v = 0.f;
    if (a <= n) {
        int ta = a >> 7, tb = n >> 6;
        int tile = (ta == 0) ? tb : 4 + (tb - 2);
        const float* bp = g_bpart[tile * 32];
        int idx = (n & 63) * 128 + (a & 127);
#pragma unroll
        for (int s = 0; s < 32; s++) v += bp[(size_t)s * 8192 + idx];
        if (a == n) v *= 0.5f;
    }
    __nv_bfloat16 h = __float2bfloat16(v);
    g_Uhi[i] = h;
    g_Ulo[i] = __float2bfloat16(v - __bfloat162float(h));
}

// ---- quad kernel (R9 proven): striped cols, double-buffer, SMEM-Y epilogue ----
#define QB(s)   ((uint32_t)(s) * 65536u)
#define QBL(s)  ((uint32_t)(s) * 65536u + 32768u)
#define QAF(s)  (131072u + (uint32_t)(s) * 32768u)
#define QAH     196608u
#define QAL     212992u
#define SMQ_TOTAL 229376
#define YSTRIDE 264   // floats

__device__ __forceinline__ void q_issue(char* smem, uint32_t sbase,
                                        const float* X, int stage, int c,
                                        int row0, int n_atoms, int t) {
    const int k0 = c * 64;
#pragma unroll
    for (int p = 0; p < 4; p++) {
        int g = t + p * 512;
        int row = g >> 4, q16 = g & 15;
        uint32_t dst = QAF(stage) + (uint32_t)(row * 256 + q16 * 16);
        if (row0 + row < n_atoms) {
            cpa16(sbase + dst, &X[(size_t)(row0 + row) * D_FEAT + k0 + q16 * 4]);
        } else {
            *(uint4*)(smem + dst) = make_uint4(0, 0, 0, 0);
        }
    }
#pragma unroll
    for (int p = 0; p < 4; p++) {
        int g = t + p * 512;
        int row = g >> 3, kq = g & 7;
        if (row >= c * 64) {
            uint32_t so = sw_off((uint32_t)(row * 128 + kq * 16));
            size_t src = (size_t)row * D_FEAT + k0 + kq * 8;
            cpa16(sbase + QB(stage) + so, &g_Uhi[src]);
            cpa16(sbase + QBL(stage) + so, &g_Ulo[src]);
        }
    }
}

__global__ void __launch_bounds__(512, 1)
k_quad_mma(const float* __restrict__ X, const int* __restrict__ rowseg,
           float* __restrict__ out, int n_atoms) {
    extern __shared__ char smem[];
    const uint32_t sbase = smem_u32(smem);
    const int t    = threadIdx.x;
    const int lane = t & 31;
    const int w    = t >> 5;
    const int wr   = w & 3;
    const int wc   = w >> 2;
    const int row0 = blockIdx.x * QM;

    float acc[2][8][4];
#pragma unroll
    for (int mt = 0; mt < 2; mt++)
#pragma unroll
        for (int nt = 0; nt < 8; nt++)
#pragma unroll
            for (int e = 0; e < 4; e++) acc[mt][nt][e] = 0.f;

    q_issue(smem, sbase, X, 0, 0, row0, n_atoms, t);
    CP_COMMIT();

#pragma unroll
    for (int c = 0; c < 4; c++) {
        const int st = c & 1;
        CP_WAIT(0);
        __syncthreads();
        if (c < 3) {
            q_issue(smem, sbase, X, 1 - st, c + 1, row0, n_atoms, t);
            CP_COMMIT();
        }
        // convert A fp32 stage -> bf16 hi/lo (SW128)
#pragma unroll
        for (int p = 0; p < 4; p++) {
            int g = t + p * 512;
            int row = g >> 4, kq = g & 15;
            float4 v = *(const float4*)(smem + QAF(st) + row * 256 + kq * 16);
            uint32_t h0, l0, h1, l1;
            bsplit(v.x, v.y, h0, l0);
            bsplit(v.z, v.w, h1, l1);
            uint32_t so = sw_off((uint32_t)(row * 128 + kq * 8));
            *(uint2*)(smem + QAH + so) = make_uint2(h0, h1);
            *(uint2*)(smem + QAL + so) = make_uint2(l0, l1);
        }
        __syncthreads();

#pragma unroll
        for (int ks = 0; ks < 4; ks++) {
            const int kk = ks * 16;
            uint32_t Ah[2][4], Al[2][4];
            ldsmA(sbase + QAH, wr * 32 + 0,  kk, lane, Ah[0]);
            ldsmA(sbase + QAH, wr * 32 + 16, kk, lane, Ah[1]);
            ldsmA(sbase + QAL, wr * 32 + 0,  kk, lane, Al[0]);
            ldsmA(sbase + QAL, wr * 32 + 16, kk, lane, Al[1]);
#pragma unroll
            for (int i = 0; i < 4; i++) {
                if (i < c) continue;              // compile-time (unrolled)
                uint32_t Bh[4], Bl[4];
                ldsmB(sbase + QB(st),  i * 64 + wc * 16, kk, lane, Bh);
                ldsmB(sbase + QBL(st), i * 64 + wc * 16, kk, lane, Bl);
#pragma unroll
                for (int mt = 0; mt < 2; mt++)
#pragma unroll
                    for (int n2 = 0; n2 < 2; n2++)
                        mma16816(acc[mt][i * 2 + n2], Ah[mt], Bh + n2 * 2);
#pragma unroll
                for (int mt = 0; mt < 2; mt++)
#pragma unroll
                    for (int n2 = 0; n2 < 2; n2++)
                        mma16816(acc[mt][i * 2 + n2], Ah[mt], Bl + n2 * 2);
#pragma unroll
                for (int mt = 0; mt < 2; mt++)
#pragma unroll
                    for (int n2 = 0; n2 < 2; n2++)
                        mma16816(acc[mt][i * 2 + n2], Al[mt], Bh + n2 * 2);
            }
        }
    }

    // ---- epilogue: fragments -> SMEM Y, then coalesced X dot ----
    __syncthreads();          // all MMA/ldmatrix done; buffers now dead
    float* Ysm = (float*)smem;
#pragma unroll
    for (int mt = 0; mt < 2; mt++)
#pragma unroll
        for (int i = 0; i < 4; i++)
#pragma unroll
            for (int n2 = 0; n2 < 2; n2++)
#pragma unroll
                for (int half = 0; half < 2; half++) {
                    int row = wr * 32 + mt * 16 + (lane >> 2) + half * 8;
                    int col = i * 64 + wc * 16 + n2 * 8 + (lane & 3) * 2;
                    float2 v = make_float2(acc[mt][i * 2 + n2][half * 2 + 0],
                                           acc[mt][i * 2 + n2][half * 2 + 1]);
                    *(float2*)&Ysm[row * YSTRIDE + col] = v;
                }
    __syncthreads();

    // pass 2: warp w owns rows w*8 .. w*8+8; coalesced X read
#pragma unroll
    for (int i = 0; i < 8; i++) {
        int rloc = w * 8 + i;
        int rg   = row0 + rloc;
        float q = 0.f, nn = 0.f;
        if (rg < n_atoms) {
#pragma unroll
            for (int k = 0; k < 4; k++) {
                float2 xv = *(const float2*)&X[(size_t)rg * D_FEAT + k * 64 + lane * 2];
                float2 yv = *(const float2*)&Ysm[rloc * YSTRIDE + k * 64 + lane * 2];
                q  = fmaf(xv.x, yv.x, q);
                q  = fmaf(xv.y, yv.y, q);
                nn = fmaf(xv.x, xv.x, nn);
                nn = fmaf(xv.y, xv.y, nn);
            }
        }
#pragma unroll
        for (int off = 16; off > 0; off >>= 1) {
            q  += __shfl_xor_sync(0xFFFFFFFFu, q, off);
            nn += __shfl_xor_sync(0xFFFFFFFFu, nn, off);
        }
        if (lane == 0 && rg < n_atoms)
            atomicAdd(&out[rowseg[rg]], 2.0f * q / nn);
    }
}

// ---- launch --------------------------------------------------------------------
extern "C" void kernel_launch(void* const* d_in, const int* in_sizes, int n_in,
                              void* d_out, int out_size) {
    const float* X      = (const float*)d_in[0];
    const float* S      = (const float*)d_in[1];
    const float* W      = (const float*)d_in[2];
    const int*   rowseg = (const int*)d_in[3];
    const int*   colseg = (const int*)d_in[4];
    float* out = (float*)d_out;

    int n_atoms   = in_sizes[0] / D_FEAT;
    int n_support = in_sizes[1] / D_FEAT;
    int n_struct  = out_size;

    cudaFuncSetAttribute(k_quad_mma, cudaFuncAttributeMaxDynamicSharedMemorySize,
                         SMQ_TOTAL);
    cudaFuncSetAttribute(k_build_mma, cudaFuncAttributeMaxDynamicSharedMemorySize,
                         SMB_TOTAL);

    k_build_mma<<<192, 256, SMB_TOTAL>>>(S, W, colseg, n_support);
    k_convM<<<D_FEAT * D_FEAT / 256, 256>>>(out, n_struct);
    int gQ = (n_atoms + QM - 1) / QM;
    k_quad_mma<<<gQ, 512, SMQ_TOTAL>>>(X, rowseg, out, n_atoms);
}

// round 13
// speedup vs baseline: 1.0884x; 1.0884x over previous
#include <cuda_runtime.h>
#include <cuda_bf16.h>
#include <cstdint>

// ============================================================================
// FullGap: out[s] = sum_{i in s} (p_i^T M p_i)/(p_i.p_i),
//          M = sum_j w[colseg[j]] s_j s_j^T  (256x256 symmetric)
// x^T M x = 2 x^T U x,  U = strict-upper(M) + diag(M)/2.
// R13: R9 proven pipeline (build 512thr/129 CTAs, convM, quad striped+SMEM-Y)
//      + diagonal-tile B-slab dedup in build (identical stride, no new layout).
// ============================================================================

#define D_FEAT 256
#define QM 128
#define NSPL 43    // splits per tile; 43*192 = 8256 >= 8192

__device__ float g_bpart[3 * NSPL][16384];                      // 8.4 MB partials
__device__ __align__(16) __nv_bfloat16 g_Uhi[D_FEAT * D_FEAT];  // [n][a]
__device__ __align__(16) __nv_bfloat16 g_Ulo[D_FEAT * D_FEAT];

// ---------------- helpers ----------------------------------------------------
__device__ __forceinline__ uint32_t smem_u32(const void* p) {
    uint32_t a;
    asm("{ .reg .u64 t; cvta.to.shared.u64 t, %1; cvt.u32.u64 %0, t; }"
        : "=r"(a) : "l"(p));
    return a;
}
__device__ __forceinline__ uint32_t sw_off(uint32_t off) {
    return off ^ ((off >> 3) & 0x70);
}
__device__ __forceinline__ void cpa16(uint32_t dst, const void* src) {
    asm volatile("cp.async.cg.shared.global [%0], [%1], 16;"
                 :: "r"(dst), "l"(__cvta_generic_to_global(src)) : "memory");
}
#define CP_COMMIT() asm volatile("cp.async.commit_group;" ::: "memory")
#define CP_WAIT(n)  asm volatile("cp.async.wait_group %0;" :: "n"(n) : "memory")

// non-trans A: smem[m][k]
__device__ __forceinline__ void ldsmA(uint32_t base, int rb, int kk, int lane,
                                      uint32_t* a) {
    int g = lane >> 3, r = lane & 7;
    int row = rb + r + (g & 1) * 8;
    int col = kk + (g >> 1) * 8;
    uint32_t addr = base + sw_off((uint32_t)(row * 128 + col * 2));
    asm volatile("ldmatrix.sync.aligned.m8n8.x4.shared.b16 {%0,%1,%2,%3}, [%4];"
                 : "=r"(a[0]), "=r"(a[1]), "=r"(a[2]), "=r"(a[3]) : "r"(addr));
}
// non-trans B: smem[n][k]
__device__ __forceinline__ void ldsmB(uint32_t base, int nb, int kk, int lane,
                                      uint32_t* b) {
    int g = lane >> 3, r = lane & 7;
    int row = nb + r + (g >> 1) * 8;
    int col = kk + (g & 1) * 8;
    uint32_t addr = base + sw_off((uint32_t)(row * 128 + col * 2));
    asm volatile("ldmatrix.sync.aligned.m8n8.x4.shared.b16 {%0,%1,%2,%3}, [%4];"
                 : "=r"(b[0]), "=r"(b[1]), "=r"(b[2]), "=r"(b[3]) : "r"(addr));
}
// trans A: smem[j][m], panels of 64 rows x 64 cols (8 KB)
__device__ __forceinline__ void ldsmT_A(uint32_t base, int ab, int kk, int lane,
                                        uint32_t* a) {
    int g = lane >> 3, r = lane & 7;
    int row = kk + r + (g >> 1) * 8;
    int col = ab + (g & 1) * 8;
    uint32_t addr = base + (uint32_t)(col >> 6) * 8192 +
                    sw_off((uint32_t)(row * 128 + (col & 63) * 2));
    asm volatile("ldmatrix.sync.aligned.m8n8.x4.trans.shared.b16 {%0,%1,%2,%3}, [%4];"
                 : "=r"(a[0]), "=r"(a[1]), "=r"(a[2]), "=r"(a[3]) : "r"(addr));
}
// trans B: smem[j][n]
__device__ __forceinline__ void ldsmT_B(uint32_t base, int nb, int kk, int lane,
                                        uint32_t* b) {
    int g = lane >> 3, r = lane & 7;
    int row = kk + r + (g & 1) * 8;
    int col = nb + (g >> 1) * 8;
    uint32_t addr = base + (uint32_t)(col >> 6) * 8192 +
                    sw_off((uint32_t)(row * 128 + (col & 63) * 2));
    asm volatile("ldmatrix.sync.aligned.m8n8.x4.trans.shared.b16 {%0,%1,%2,%3}, [%4];"
                 : "=r"(b[0]), "=r"(b[1]), "=r"(b[2]), "=r"(b[3]) : "r"(addr));
}
__device__ __forceinline__ void mma16816(float* c, const uint32_t* a,
                                         const uint32_t* b) {
    asm volatile(
        "mma.sync.aligned.m16n8k16.row.col.f32.bf16.bf16.f32 "
        "{%0,%1,%2,%3}, {%4,%5,%6,%7}, {%8,%9}, {%0,%1,%2,%3};"
        : "+f"(c[0]), "+f"(c[1]), "+f"(c[2]), "+f"(c[3])
        : "r"(a[0]), "r"(a[1]), "r"(a[2]), "r"(a[3]), "r"(b[0]), "r"(b[1]));
}
__device__ __forceinline__ void bsplit(float x, float y, uint32_t& hi, uint32_t& lo) {
    float hx = __bfloat162float(__float2bfloat16(x));
    float hy = __bfloat162float(__float2bfloat16(y));
    __nv_bfloat162 h = __floats2bfloat162_rn(hx, hy);
    __nv_bfloat162 l = __floats2bfloat162_rn(x - hx, y - hy);
    hi = *(uint32_t*)&h;
    lo = *(uint32_t*)&l;
}

// ---- build (R9 + diag dedup): M[a,b] = sum_j S[j][a] * w_j S[j][b] ------------
// 129 CTAs = 3 tiles x 43 splits. 512 thr. 192 j per CTA, 3 chunks of 64,
// double-buffered. Diagonal tiles (0,2) skip the B slab load (same data as A).
#define FB_A(s) ((uint32_t)(s) * 32768u)
#define FB_B(s) (65536u + (uint32_t)(s) * 32768u)
#define BAH 131072u
#define BAL 147456u
#define BBH 163840u
#define BBL 180224u
#define BWO 196608u
#define SMB_TOTAL 197632

__device__ __forceinline__ void b_issue(char* smem, uint32_t sbase,
                                        const float* S, int stage, int jb,
                                        int a0, int b0, bool same,
                                        int n_support, int t) {
#pragma unroll
    for (int p = 0; p < 4; p++) {
        int g = t + p * 512;          // 2048 granules = 64 j x 32 float4
        int jl = g >> 5, cq = g & 31;
        int jg = jb + jl;
        uint32_t dst = FB_A(stage) + (uint32_t)(jl * 512 + cq * 16);
        if (jg < n_support)
            cpa16(sbase + dst, &S[(size_t)jg * D_FEAT + a0 + cq * 4]);
        else
            *(uint4*)(smem + dst) = make_uint4(0, 0, 0, 0);
    }
    if (!same) {
#pragma unroll
        for (int p = 0; p < 4; p++) {
            int g = t + p * 512;
            int jl = g >> 5, cq = g & 31;
            int jg = jb + jl;
            uint32_t dst = FB_B(stage) + (uint32_t)(jl * 512 + cq * 16);
            if (jg < n_support)
                cpa16(sbase + dst, &S[(size_t)jg * D_FEAT + b0 + cq * 4]);
            else
                *(uint4*)(smem + dst) = make_uint4(0, 0, 0, 0);
        }
    }
}

__global__ void __launch_bounds__(512, 1)
k_build_mma(const float* __restrict__ S, const float* __restrict__ W,
            const int* __restrict__ colseg, int n_support) {
    extern __shared__ char smem[];
    const uint32_t sbase = smem_u32(smem);
    float* wsm = (float*)(smem + BWO);
    const int t    = threadIdx.x;
    const int lane = t & 31;
    const int w    = t >> 5;
    const int wr   = w & 3;
    const int wc   = w >> 2;

    const int tile  = blockIdx.x / NSPL;
    const int split = blockIdx.x % NSPL;
    const int a0 = (tile == 2) ? 128 : 0;
    const int b0 = (tile == 0) ? 0 : 128;
    const bool same = (tile != 1);       // diagonal tiles share the slab
    const int jorg = split * 192;

    if (t < 192) {
        int jg = jorg + t;
        wsm[t] = (jg < n_support) ? W[colseg[jg]] : 0.f;
    }

    b_issue(smem, sbase, S, 0, jorg, a0, b0, same, n_support, t);
    CP_COMMIT();

    float acc[2][4][4];
#pragma unroll
    for (int mt = 0; mt < 2; mt++)
#pragma unroll
        for (int nt = 0; nt < 4; nt++)
#pragma unroll
            for (int e = 0; e < 4; e++) acc[mt][nt][e] = 0.f;

#pragma unroll 1
    for (int c = 0; c < 3; c++) {
        const int st = c & 1;
        if (c < 2) {
            b_issue(smem, sbase, S, 1 - st, jorg + (c + 1) * 64, a0, b0, same,
                    n_support, t);
            CP_COMMIT();
            CP_WAIT(1);
        } else {
            CP_WAIT(0);
        }
        __syncthreads();

        // convert A: fp32 -> bf16 hi/lo trans panels
#pragma unroll
        for (int p = 0; p < 4; p++) {
            int g = t + p * 512;
            int jl = g >> 5, cq = g & 31;
            float4 v = *(const float4*)(smem + FB_A(st) + jl * 512 + cq * 16);
            uint32_t h0, l0, h1, l1;
            bsplit(v.x, v.y, h0, l0);
            bsplit(v.z, v.w, h1, l1);
            uint32_t off = (uint32_t)(cq >> 4) * 8192 +
                           sw_off((uint32_t)(jl * 128 + (cq & 15) * 8));
            *(uint2*)(smem + BAH + off) = make_uint2(h0, h1);
            *(uint2*)(smem + BAL + off) = make_uint2(l0, l1);
        }
        // convert B: w_j * fp32 -> bf16 hi/lo (same slab for diag tiles,
        // identical 512B row stride either way)
#pragma unroll
        for (int p = 0; p < 4; p++) {
            int g = t + p * 512;
            int jl = g >> 5, cq = g & 31;
            uint32_t src = (same ? FB_A(st) : FB_B(st)) +
                           (uint32_t)(jl * 512 + cq * 16);
            float4 v = *(const float4*)(smem + src);
            float wj = wsm[c * 64 + jl];
            uint32_t h0, l0, h1, l1;
            bsplit(wj * v.x, wj * v.y, h0, l0);
            bsplit(wj * v.z, wj * v.w, h1, l1);
            uint32_t off = (uint32_t)(cq >> 4) * 8192 +
                           sw_off((uint32_t)(jl * 128 + (cq & 15) * 8));
            *(uint2*)(smem + BBH + off) = make_uint2(h0, h1);
            *(uint2*)(smem + BBL + off) = make_uint2(l0, l1);
        }
        __syncthreads();

#pragma unroll
        for (int ks = 0; ks < 4; ks++) {
            const int kk = ks * 16;
            uint32_t Ah[2][4], Al[2][4], Bh[2][4], Bl[2][4];
            ldsmT_A(sbase + BAH, wr * 32 + 0,  kk, lane, Ah[0]);
            ldsmT_A(sbase + BAH, wr * 32 + 16, kk, lane, Ah[1]);
            ldsmT_A(sbase + BAL, wr * 32 + 0,  kk, lane, Al[0]);
            ldsmT_A(sbase + BAL, wr * 32 + 16, kk, lane, Al[1]);
            ldsmT_B(sbase + BBH, wc * 32 + 0,  kk, lane, Bh[0]);
            ldsmT_B(sbase + BBH, wc * 32 + 16, kk, lane, Bh[1]);
            ldsmT_B(sbase + BBL, wc * 32 + 0,  kk, lane, Bl[0]);
            ldsmT_B(sbase + BBL, wc * 32 + 16, kk, lane, Bl[1]);
#pragma unroll
            for (int np = 0; np < 2; np++)
#pragma unroll
                for (int mt = 0; mt < 2; mt++)
#pragma unroll
                    for (int n2 = 0; n2 < 2; n2++)
                        mma16816(acc[mt][np * 2 + n2], Ah[mt], Bh[np] + n2 * 2);
#pragma unroll
            for (int np = 0; np < 2; np++)
#pragma unroll
                for (int mt = 0; mt < 2; mt++)
#pragma unroll
                    for (int n2 = 0; n2 < 2; n2++)
                        mma16816(acc[mt][np * 2 + n2], Ah[mt], Bl[np] + n2 * 2);
#pragma unroll
            for (int np = 0; np < 2; np++)
#pragma unroll
                for (int mt = 0; mt < 2; mt++)
#pragma unroll
                    for (int n2 = 0; n2 < 2; n2++)
                        mma16816(acc[mt][np * 2 + n2], Al[mt], Bh[np] + n2 * 2);
        }
    }

    __syncthreads();
    float* stg = (float*)smem;
#pragma unroll
    for (int mt = 0; mt < 2; mt++)
#pragma unroll
        for (int nt = 0; nt < 4; nt++)
#pragma unroll
            for (int e = 0; e < 4; e++) {
                int a = wr * 32 + mt * 16 + (lane >> 2) + (e >> 1) * 8;
                int b = wc * 32 + nt * 8 + (lane & 3) * 2 + (e & 1);
                stg[b * 128 + a] = acc[mt][nt][e];
            }
    __syncthreads();
    float* dst = g_bpart[blockIdx.x];
#pragma unroll
    for (int i = 0; i < 32; i++)
        dst[i * 512 + t] = stg[i * 512 + t];
}

// ---- convM: reduce partials -> U bf16 hi/lo, zero out -------------------------
__global__ void k_convM(float* __restrict__ out, int n_struct) {
    int i = blockIdx.x * blockDim.x + threadIdx.x;   // 65536, i = n*256+a
    if (i < n_struct) out[i] = 0.f;
    int a = i & 255, n = i >> 8;
    float v = 0.f;
    if (a <= n) {
        int tile = (n < 128) ? 0 : ((a < 128) ? 1 : 2);
        int idx = (n & 127) * 128 + (a & 127);
        const float* bp = g_bpart[tile * NSPL];
#pragma unroll
        for (int s = 0; s < NSPL; s++) v += bp[(size_t)s * 16384 + idx];
        if (a == n) v *= 0.5f;
    }
    __nv_bfloat16 h = __float2bfloat16(v);
    g_Uhi[i] = h;
    g_Ulo[i] = __float2bfloat16(v - __bfloat162float(h));
}

// ---- quad kernel (R9 proven): striped cols, double-buffer, SMEM-Y epilogue ----
#define QB(s)   ((uint32_t)(s) * 65536u)
#define QBL(s)  ((uint32_t)(s) * 65536u + 32768u)
#define QAF(s)  (131072u + (uint32_t)(s) * 32768u)
#define QAH     196608u
#define QAL     212992u
#define SMQ_TOTAL 229376
#define YSTRIDE 264   // floats

__device__ __forceinline__ void q_issue(char* smem, uint32_t sbase,
                                        const float* X, int stage, int c,
                                        int row0, int n_atoms, int t) {
    const int k0 = c * 64;
#pragma unroll
    for (int p = 0; p < 4; p++) {
        int g = t + p * 512;
        int row = g >> 4, q16 = g & 15;
        uint32_t dst = QAF(stage) + (uint32_t)(row * 256 + q16 * 16);
        if (row0 + row < n_atoms) {
            cpa16(sbase + dst, &X[(size_t)(row0 + row) * D_FEAT + k0 + q16 * 4]);
        } else {
            *(uint4*)(smem + dst) = make_uint4(0, 0, 0, 0);
        }
    }
#pragma unroll
    for (int p = 0; p < 4; p++) {
        int g = t + p * 512;
        int row = g >> 3, kq = g & 7;
        if (row >= c * 64) {
            uint32_t so = sw_off((uint32_t)(row * 128 + kq * 16));
            size_t src = (size_t)row * D_FEAT + k0 + kq * 8;
            cpa16(sbase + QB(stage) + so, &g_Uhi[src]);
            cpa16(sbase + QBL(stage) + so, &g_Ulo[src]);
        }
    }
}

__global__ void __launch_bounds__(512, 1)
k_quad_mma(const float* __restrict__ X, const int* __restrict__ rowseg,
           float* __restrict__ out, int n_atoms) {
    extern __shared__ char smem[];
    const uint32_t sbase = smem_u32(smem);
    const int t    = threadIdx.x;
    const int lane = t & 31;
    const int w    = t >> 5;
    const int wr   = w & 3;
    const int wc   = w >> 2;
    const int row0 = blockIdx.x * QM;

    float acc[2][8][4];
#pragma unroll
    for (int mt = 0; mt < 2; mt++)
#pragma unroll
        for (int nt = 0; nt < 8; nt++)
#pragma unroll
            for (int e = 0; e < 4; e++) acc[mt][nt][e] = 0.f;

    q_issue(smem, sbase, X, 0, 0, row0, n_atoms, t);
    CP_COMMIT();

#pragma unroll
    for (int c = 0; c < 4; c++) {
        const int st = c & 1;
        CP_WAIT(0);
        __syncthreads();
        if (c < 3) {
            q_issue(smem, sbase, X, 1 - st, c + 1, row0, n_atoms, t);
            CP_COMMIT();
        }
        // convert A fp32 stage -> bf16 hi/lo (SW128)
#pragma unroll
        for (int p = 0; p < 4; p++) {
            int g = t + p * 512;
            int row = g >> 4, kq = g & 15;
            float4 v = *(const float4*)(smem + QAF(st) + row * 256 + kq * 16);
            uint32_t h0, l0, h1, l1;
            bsplit(v.x, v.y, h0, l0);
            bsplit(v.z, v.w, h1, l1);
            uint32_t so = sw_off((uint32_t)(row * 128 + kq * 8));
            *(uint2*)(smem + QAH + so) = make_uint2(h0, h1);
            *(uint2*)(smem + QAL + so) = make_uint2(l0, l1);
        }
        __syncthreads();

#pragma unroll
        for (int ks = 0; ks < 4; ks++) {
            const int kk = ks * 16;
            uint32_t Ah[2][4], Al[2][4];
            ldsmA(sbase + QAH, wr * 32 + 0,  kk, lane, Ah[0]);
            ldsmA(sbase + QAH, wr * 32 + 16, kk, lane, Ah[1]);
            ldsmA(sbase + QAL, wr * 32 + 0,  kk, lane, Al[0]);
            ldsmA(sbase + QAL, wr * 32 + 16, kk, lane, Al[1]);
#pragma unroll
            for (int i = 0; i < 4; i++) {
                if (i < c) continue;              // compile-time (unrolled)
                uint32_t Bh[4], Bl[4];
                ldsmB(sbase + QB(st),  i * 64 + wc * 16, kk, lane, Bh);
                ldsmB(sbase + QBL(st), i * 64 + wc * 16, kk, lane, Bl);
#pragma unroll
                for (int mt = 0; mt < 2; mt++)
#pragma unroll
                    for (int n2 = 0; n2 < 2; n2++)
                        mma16816(acc[mt][i * 2 + n2], Ah[mt], Bh + n2 * 2);
#pragma unroll
                for (int mt = 0; mt < 2; mt++)
#pragma unroll
                    for (int n2 = 0; n2 < 2; n2++)
                        mma16816(acc[mt][i * 2 + n2], Ah[mt], Bl + n2 * 2);
#pragma unroll
                for (int mt = 0; mt < 2; mt++)
#pragma unroll
                    for (int n2 = 0; n2 < 2; n2++)
                        mma16816(acc[mt][i * 2 + n2], Al[mt], Bh + n2 * 2);
            }
        }
    }

    // ---- epilogue: fragments -> SMEM Y, then coalesced X dot ----
    __syncthreads();          // all MMA/ldmatrix done; buffers now dead
    float* Ysm = (float*)smem;
#pragma unroll
    for (int mt = 0; mt < 2; mt++)
#pragma unroll
        for (int i = 0; i < 4; i++)
#pragma unroll
            for (int n2 = 0; n2 < 2; n2++)
#pragma unroll
                for (int half = 0; half < 2; half++) {
                    int row = wr * 32 + mt * 16 + (lane >> 2) + half * 8;
                    int col = i * 64 + wc * 16 + n2 * 8 + (lane & 3) * 2;
                    float2 v = make_float2(acc[mt][i * 2 + n2][half * 2 + 0],
                                           acc[mt][i * 2 + n2][half * 2 + 1]);
                    *(float2*)&Ysm[row * YSTRIDE + col] = v;
                }
    __syncthreads();

    // pass 2: warp w owns rows w*8 .. w*8+8; coalesced X read
#pragma unroll
    for (int i = 0; i < 8; i++) {
        int rloc = w * 8 + i;
        int rg   = row0 + rloc;
        float q = 0.f, nn = 0.f;
        if (rg < n_atoms) {
#pragma unroll
            for (int k = 0; k < 4; k++) {
                float2 xv = *(const float2*)&X[(size_t)rg * D_FEAT + k * 64 + lane * 2];
                float2 yv = *(const float2*)&Ysm[rloc * YSTRIDE + k * 64 + lane * 2];
                q  = fmaf(xv.x, yv.x, q);
                q  = fmaf(xv.y, yv.y, q);
                nn = fmaf(xv.x, xv.x, nn);
                nn = fmaf(xv.y, xv.y, nn);
            }
        }
#pragma unroll
        for (int off = 16; off > 0; off >>= 1) {
            q  += __shfl_xor_sync(0xFFFFFFFFu, q, off);
            nn += __shfl_xor_sync(0xFFFFFFFFu, nn, off);
        }
        if (lane == 0 && rg < n_atoms)
            atomicAdd(&out[rowseg[rg]], 2.0f * q / nn);
    }
}

// ---- launch --------------------------------------------------------------------
extern "C" void kernel_launch(void* const* d_in, const int* in_sizes, int n_in,
                              void* d_out, int out_size) {
    const float* X      = (const float*)d_in[0];
    const float* S      = (const float*)d_in[1];
    const float* W      = (const float*)d_in[2];
    const int*   rowseg = (const int*)d_in[3];
    const int*   colseg = (const int*)d_in[4];
    float* out = (float*)d_out;

    int n_atoms   = in_sizes[0] / D_FEAT;
    int n_support = in_sizes[1] / D_FEAT;
    int n_struct  = out_size;

    cudaFuncSetAttribute(k_quad_mma, cudaFuncAttributeMaxDynamicSharedMemorySize,
                         SMQ_TOTAL);
    cudaFuncSetAttribute(k_build_mma, cudaFuncAttributeMaxDynamicSharedMemorySize,
                         SMB_TOTAL);

    k_build_mma<<<3 * NSPL, 512, SMB_TOTAL>>>(S, W, colseg, n_support);
    k_convM<<<D_FEAT * D_FEAT / 256, 256>>>(out, n_struct);
    int gQ = (n_atoms + QM - 1) / QM;
    k_quad_mma<<<gQ, 512, SMQ_TOTAL>>>(X, rowseg, out, n_atoms);
}

// round 14
// speedup vs baseline: 1.1137x; 1.0232x over previous
#include <cuda_runtime.h>
#include <cuda_bf16.h>
#include <cstdint>

// ============================================================================
// FullGap: out[s] = sum_{i in s} (p_i^T M p_i)/(p_i.p_i),
//          M = sum_j w[colseg[j]] s_j s_j^T  (256x256 symmetric)
// x^T M x = 2 x^T U x,  U = strict-upper(M) + diag(M)/2.
// R14: R13 proven pipeline + exact diagonal-block skip in quad
//      (fragment (ks>wc) of stripe i==c multiplies an all-zero U block).
// ============================================================================

#define D_FEAT 256
#define QM 128
#define NSPL 43    // splits per tile; 43*192 = 8256 >= 8192

__device__ float g_bpart[3 * NSPL][16384];                      // 8.4 MB partials
__device__ __align__(16) __nv_bfloat16 g_Uhi[D_FEAT * D_FEAT];  // [n][a]
__device__ __align__(16) __nv_bfloat16 g_Ulo[D_FEAT * D_FEAT];

// ---------------- helpers ----------------------------------------------------
__device__ __forceinline__ uint32_t smem_u32(const void* p) {
    uint32_t a;
    asm("{ .reg .u64 t; cvta.to.shared.u64 t, %1; cvt.u32.u64 %0, t; }"
        : "=r"(a) : "l"(p));
    return a;
}
__device__ __forceinline__ uint32_t sw_off(uint32_t off) {
    return off ^ ((off >> 3) & 0x70);
}
__device__ __forceinline__ void cpa16(uint32_t dst, const void* src) {
    asm volatile("cp.async.cg.shared.global [%0], [%1], 16;"
                 :: "r"(dst), "l"(__cvta_generic_to_global(src)) : "memory");
}
#define CP_COMMIT() asm volatile("cp.async.commit_group;" ::: "memory")
#define CP_WAIT(n)  asm volatile("cp.async.wait_group %0;" :: "n"(n) : "memory")

// non-trans A: smem[m][k]
__device__ __forceinline__ void ldsmA(uint32_t base, int rb, int kk, int lane,
                                      uint32_t* a) {
    int g = lane >> 3, r = lane & 7;
    int row = rb + r + (g & 1) * 8;
    int col = kk + (g >> 1) * 8;
    uint32_t addr = base + sw_off((uint32_t)(row * 128 + col * 2));
    asm volatile("ldmatrix.sync.aligned.m8n8.x4.shared.b16 {%0,%1,%2,%3}, [%4];"
                 : "=r"(a[0]), "=r"(a[1]), "=r"(a[2]), "=r"(a[3]) : "r"(addr));
}
// non-trans B: smem[n][k]
__device__ __forceinline__ void ldsmB(uint32_t base, int nb, int kk, int lane,
                                      uint32_t* b) {
    int g = lane >> 3, r = lane & 7;
    int row = nb + r + (g >> 1) * 8;
    int col = kk + (g & 1) * 8;
    uint32_t addr = base + sw_off((uint32_t)(row * 128 + col * 2));
    asm volatile("ldmatrix.sync.aligned.m8n8.x4.shared.b16 {%0,%1,%2,%3}, [%4];"
                 : "=r"(b[0]), "=r"(b[1]), "=r"(b[2]), "=r"(b[3]) : "r"(addr));
}
// trans A: smem[j][m], panels of 64 rows x 64 cols (8 KB)
__device__ __forceinline__ void ldsmT_A(uint32_t base, int ab, int kk, int lane,
                                        uint32_t* a) {
    int g = lane >> 3, r = lane & 7;
    int row = kk + r + (g >> 1) * 8;
    int col = ab + (g & 1) * 8;
    uint32_t addr = base + (uint32_t)(col >> 6) * 8192 +
                    sw_off((uint32_t)(row * 128 + (col & 63) * 2));
    asm volatile("ldmatrix.sync.aligned.m8n8.x4.trans.shared.b16 {%0,%1,%2,%3}, [%4];"
                 : "=r"(a[0]), "=r"(a[1]), "=r"(a[2]), "=r"(a[3]) : "r"(addr));
}
// trans B: smem[j][n]
__device__ __forceinline__ void ldsmT_B(uint32_t base, int nb, int kk, int lane,
                                        uint32_t* b) {
    int g = lane >> 3, r = lane & 7;
    int row = kk + r + (g & 1) * 8;
    int col = nb + (g >> 1) * 8;
    uint32_t addr = base + (uint32_t)(col >> 6) * 8192 +
                    sw_off((uint32_t)(row * 128 + (col & 63) * 2));
    asm volatile("ldmatrix.sync.aligned.m8n8.x4.trans.shared.b16 {%0,%1,%2,%3}, [%4];"
                 : "=r"(b[0]), "=r"(b[1]), "=r"(b[2]), "=r"(b[3]) : "r"(addr));
}
__device__ __forceinline__ void mma16816(float* c, const uint32_t* a,
                                         const uint32_t* b) {
    asm volatile(
        "mma.sync.aligned.m16n8k16.row.col.f32.bf16.bf16.f32 "
        "{%0,%1,%2,%3}, {%4,%5,%6,%7}, {%8,%9}, {%0,%1,%2,%3};"
        : "+f"(c[0]), "+f"(c[1]), "+f"(c[2]), "+f"(c[3])
        : "r"(a[0]), "r"(a[1]), "r"(a[2]), "r"(a[3]), "r"(b[0]), "r"(b[1]));
}
__device__ __forceinline__ void bsplit(float x, float y, uint32_t& hi, uint32_t& lo) {
    float hx = __bfloat162float(__float2bfloat16(x));
    float hy = __bfloat162float(__float2bfloat16(y));
    __nv_bfloat162 h = __floats2bfloat162_rn(hx, hy);
    __nv_bfloat162 l = __floats2bfloat162_rn(x - hx, y - hy);
    hi = *(uint32_t*)&h;
    lo = *(uint32_t*)&l;
}

// ---- build (R13): M[a,b] = sum_j S[j][a] * w_j S[j][b] ------------------------
#define FB_A(s) ((uint32_t)(s) * 32768u)
#define FB_B(s) (65536u + (uint32_t)(s) * 32768u)
#define BAH 131072u
#define BAL 147456u
#define BBH 163840u
#define BBL 180224u
#define BWO 196608u
#define SMB_TOTAL 197632

__device__ __forceinline__ void b_issue(char* smem, uint32_t sbase,
                                        const float* S, int stage, int jb,
                                        int a0, int b0, bool same,
                                        int n_support, int t) {
#pragma unroll
    for (int p = 0; p < 4; p++) {
        int g = t + p * 512;          // 2048 granules = 64 j x 32 float4
        int jl = g >> 5, cq = g & 31;
        int jg = jb + jl;
        uint32_t dst = FB_A(stage) + (uint32_t)(jl * 512 + cq * 16);
        if (jg < n_support)
            cpa16(sbase + dst, &S[(size_t)jg * D_FEAT + a0 + cq * 4]);
        else
            *(uint4*)(smem + dst) = make_uint4(0, 0, 0, 0);
    }
    if (!same) {
#pragma unroll
        for (int p = 0; p < 4; p++) {
            int g = t + p * 512;
            int jl = g >> 5, cq = g & 31;
            int jg = jb + jl;
            uint32_t dst = FB_B(stage) + (uint32_t)(jl * 512 + cq * 16);
            if (jg < n_support)
                cpa16(sbase + dst, &S[(size_t)jg * D_FEAT + b0 + cq * 4]);
            else
                *(uint4*)(smem + dst) = make_uint4(0, 0, 0, 0);
        }
    }
}

__global__ void __launch_bounds__(512, 1)
k_build_mma(const float* __restrict__ S, const float* __restrict__ W,
            const int* __restrict__ colseg, int n_support) {
    extern __shared__ char smem[];
    const uint32_t sbase = smem_u32(smem);
    float* wsm = (float*)(smem + BWO);
    const int t    = threadIdx.x;
    const int lane = t & 31;
    const int w    = t >> 5;
    const int wr   = w & 3;
    const int wc   = w >> 2;

    const int tile  = blockIdx.x / NSPL;
    const int split = blockIdx.x % NSPL;
    const int a0 = (tile == 2) ? 128 : 0;
    const int b0 = (tile == 0) ? 0 : 128;
    const bool same = (tile != 1);       // diagonal tiles share the slab
    const int jorg = split * 192;

    if (t < 192) {
        int jg = jorg + t;
        wsm[t] = (jg < n_support) ? W[colseg[jg]] : 0.f;
    }

    b_issue(smem, sbase, S, 0, jorg, a0, b0, same, n_support, t);
    CP_COMMIT();

    float acc[2][4][4];
#pragma unroll
    for (int mt = 0; mt < 2; mt++)
#pragma unroll
        for (int nt = 0; nt < 4; nt++)
#pragma unroll
            for (int e = 0; e < 4; e++) acc[mt][nt][e] = 0.f;

#pragma unroll 1
    for (int c = 0; c < 3; c++) {
        const int st = c & 1;
        if (c < 2) {
            b_issue(smem, sbase, S, 1 - st, jorg + (c + 1) * 64, a0, b0, same,
                    n_support, t);
            CP_COMMIT();
            CP_WAIT(1);
        } else {
            CP_WAIT(0);
        }
        __syncthreads();

        // convert A: fp32 -> bf16 hi/lo trans panels
#pragma unroll
        for (int p = 0; p < 4; p++) {
            int g = t + p * 512;
            int jl = g >> 5, cq = g & 31;
            float4 v = *(const float4*)(smem + FB_A(st) + jl * 512 + cq * 16);
            uint32_t h0, l0, h1, l1;
            bsplit(v.x, v.y, h0, l0);
            bsplit(v.z, v.w, h1, l1);
            uint32_t off = (uint32_t)(cq >> 4) * 8192 +
                           sw_off((uint32_t)(jl * 128 + (cq & 15) * 8));
            *(uint2*)(smem + BAH + off) = make_uint2(h0, h1);
            *(uint2*)(smem + BAL + off) = make_uint2(l0, l1);
        }
        // convert B: w_j * fp32 -> bf16 hi/lo (same slab for diag tiles)
#pragma unroll
        for (int p = 0; p < 4; p++) {
            int g = t + p * 512;
            int jl = g >> 5, cq = g & 31;
            uint32_t src = (same ? FB_A(st) : FB_B(st)) +
                           (uint32_t)(jl * 512 + cq * 16);
            float4 v = *(const float4*)(smem + src);
            float wj = wsm[c * 64 + jl];
            uint32_t h0, l0, h1, l1;
            bsplit(wj * v.x, wj * v.y, h0, l0);
            bsplit(wj * v.z, wj * v.w, h1, l1);
            uint32_t off = (uint32_t)(cq >> 4) * 8192 +
                           sw_off((uint32_t)(jl * 128 + (cq & 15) * 8));
            *(uint2*)(smem + BBH + off) = make_uint2(h0, h1);
            *(uint2*)(smem + BBL + off) = make_uint2(l0, l1);
        }
        __syncthreads();

#pragma unroll
        for (int ks = 0; ks < 4; ks++) {
            const int kk = ks * 16;
            uint32_t Ah[2][4], Al[2][4], Bh[2][4], Bl[2][4];
            ldsmT_A(sbase + BAH, wr * 32 + 0,  kk, lane, Ah[0]);
            ldsmT_A(sbase + BAH, wr * 32 + 16, kk, lane, Ah[1]);
            ldsmT_A(sbase + BAL, wr * 32 + 0,  kk, lane, Al[0]);
            ldsmT_A(sbase + BAL, wr * 32 + 16, kk, lane, Al[1]);
            ldsmT_B(sbase + BBH, wc * 32 + 0,  kk, lane, Bh[0]);
            ldsmT_B(sbase + BBH, wc * 32 + 16, kk, lane, Bh[1]);
            ldsmT_B(sbase + BBL, wc * 32 + 0,  kk, lane, Bl[0]);
            ldsmT_B(sbase + BBL, wc * 32 + 16, kk, lane, Bl[1]);
#pragma unroll
            for (int np = 0; np < 2; np++)
#pragma unroll
                for (int mt = 0; mt < 2; mt++)
#pragma unroll
                    for (int n2 = 0; n2 < 2; n2++)
                        mma16816(acc[mt][np * 2 + n2], Ah[mt], Bh[np] + n2 * 2);
#pragma unroll
            for (int np = 0; np < 2; np++)
#pragma unroll
                for (int mt = 0; mt < 2; mt++)
#pragma unroll
                    for (int n2 = 0; n2 < 2; n2++)
                        mma16816(acc[mt][np * 2 + n2], Ah[mt], Bl[np] + n2 * 2);
#pragma unroll
            for (int np = 0; np < 2; np++)
#pragma unroll
                for (int mt = 0; mt < 2; mt++)
#pragma unroll
                    for (int n2 = 0; n2 < 2; n2++)
                        mma16816(acc[mt][np * 2 + n2], Al[mt], Bh[np] + n2 * 2);
        }
    }

    __syncthreads();
    float* stg = (float*)smem;
#pragma unroll
    for (int mt = 0; mt < 2; mt++)
#pragma unroll
        for (int nt = 0; nt < 4; nt++)
#pragma unroll
            for (int e = 0; e < 4; e++) {
                int a = wr * 32 + mt * 16 + (lane >> 2) + (e >> 1) * 8;
                int b = wc * 32 + nt * 8 + (lane & 3) * 2 + (e & 1);
                stg[b * 128 + a] = acc[mt][nt][e];
            }
    __syncthreads();
    float* dst = g_bpart[blockIdx.x];
#pragma unroll
    for (int i = 0; i < 32; i++)
        dst[i * 512 + t] = stg[i * 512 + t];
}

// ---- convM: reduce partials -> U bf16 hi/lo, zero out -------------------------
__global__ void k_convM(float* __restrict__ out, int n_struct) {
    int i = blockIdx.x * blockDim.x + threadIdx.x;   // 65536, i = n*256+a
    if (i < n_struct) out[i] = 0.f;
    int a = i & 255, n = i >> 8;
    float v = 0.f;
    if (a <= n) {
        int tile = (n < 128) ? 0 : ((a < 128) ? 1 : 2);
        int idx = (n & 127) * 128 + (a & 127);
        const float* bp = g_bpart[tile * NSPL];
#pragma unroll
        for (int s = 0; s < NSPL; s++) v += bp[(size_t)s * 16384 + idx];
        if (a == n) v *= 0.5f;
    }
    __nv_bfloat16 h = __float2bfloat16(v);
    g_Uhi[i] = h;
    g_Ulo[i] = __float2bfloat16(v - __bfloat162float(h));
}

// ---- quad kernel: striped cols + diagonal-block skip, SMEM-Y epilogue ---------
#define QB(s)   ((uint32_t)(s) * 65536u)
#define QBL(s)  ((uint32_t)(s) * 65536u + 32768u)
#define QAF(s)  (131072u + (uint32_t)(s) * 32768u)
#define QAH     196608u
#define QAL     212992u
#define SMQ_TOTAL 229376
#define YSTRIDE 264   // floats

__device__ __forceinline__ void q_issue(char* smem, uint32_t sbase,
                                        const float* X, int stage, int c,
                                        int row0, int n_atoms, int t) {
    const int k0 = c * 64;
#pragma unroll
    for (int p = 0; p < 4; p++) {
        int g = t + p * 512;
        int row = g >> 4, q16 = g & 15;
        uint32_t dst = QAF(stage) + (uint32_t)(row * 256 + q16 * 16);
        if (row0 + row < n_atoms) {
            cpa16(sbase + dst, &X[(size_t)(row0 + row) * D_FEAT + k0 + q16 * 4]);
        } else {
            *(uint4*)(smem + dst) = make_uint4(0, 0, 0, 0);
        }
    }
#pragma unroll
    for (int p = 0; p < 4; p++) {
        int g = t + p * 512;
        int row = g >> 3, kq = g & 7;
        if (row >= c * 64) {
            uint32_t so = sw_off((uint32_t)(row * 128 + kq * 16));
            size_t src = (size_t)row * D_FEAT + k0 + kq * 8;
            cpa16(sbase + QB(stage) + so, &g_Uhi[src]);
            cpa16(sbase + QBL(stage) + so, &g_Ulo[src]);
        }
    }
}

__global__ void __launch_bounds__(512, 1)
k_quad_mma(const float* __restrict__ X, const int* __restrict__ rowseg,
           float* __restrict__ out, int n_atoms) {
    extern __shared__ char smem[];
    const uint32_t sbase = smem_u32(smem);
    const int t    = threadIdx.x;
    const int lane = t & 31;
    const int w    = t >> 5;
    const int wr   = w & 3;
    const int wc   = w >> 2;
    const int row0 = blockIdx.x * QM;

    float acc[2][8][4];
#pragma unroll
    for (int mt = 0; mt < 2; mt++)
#pragma unroll
        for (int nt = 0; nt < 8; nt++)
#pragma unroll
            for (int e = 0; e < 4; e++) acc[mt][nt][e] = 0.f;

    q_issue(smem, sbase, X, 0, 0, row0, n_atoms, t);
    CP_COMMIT();

#pragma unroll
    for (int c = 0; c < 4; c++) {
        const int st = c & 1;
        CP_WAIT(0);
        __syncthreads();
        if (c < 3) {
            q_issue(smem, sbase, X, 1 - st, c + 1, row0, n_atoms, t);
            CP_COMMIT();
        }
        // convert A fp32 stage -> bf16 hi/lo (SW128)
#pragma unroll
        for (int p = 0; p < 4; p++) {
            int g = t + p * 512;
            int row = g >> 4, kq = g & 15;
            float4 v = *(const float4*)(smem + QAF(st) + row * 256 + kq * 16);
            uint32_t h0, l0, h1, l1;
            bsplit(v.x, v.y, h0, l0);
            bsplit(v.z, v.w, h1, l1);
            uint32_t so = sw_off((uint32_t)(row * 128 + kq * 8));
            *(uint2*)(smem + QAH + so) = make_uint2(h0, h1);
            *(uint2*)(smem + QAL + so) = make_uint2(l0, l1);
        }
        __syncthreads();

#pragma unroll
        for (int ks = 0; ks < 4; ks++) {
            const int kk = ks * 16;
            uint32_t Ah[2][4], Al[2][4];
            ldsmA(sbase + QAH, wr * 32 + 0,  kk, lane, Ah[0]);
            ldsmA(sbase + QAH, wr * 32 + 16, kk, lane, Ah[1]);
            ldsmA(sbase + QAL, wr * 32 + 0,  kk, lane, Al[0]);
            ldsmA(sbase + QAL, wr * 32 + 16, kk, lane, Al[1]);
#pragma unroll
            for (int i = 0; i < 4; i++) {
                if (i < c) continue;              // stripe fully below diagonal
                if (i == c && ks > wc) continue;  // diagonal block: U == 0 exactly
                uint32_t Bh[4], Bl[4];
                ldsmB(sbase + QB(st),  i * 64 + wc * 16, kk, lane, Bh);
                ldsmB(sbase + QBL(st), i * 64 + wc * 16, kk, lane, Bl);
#pragma unroll
                for (int mt = 0; mt < 2; mt++)
#pragma unroll
                    for (int n2 = 0; n2 < 2; n2++)
                        mma16816(acc[mt][i * 2 + n2], Ah[mt], Bh + n2 * 2);
#pragma unroll
                for (int mt = 0; mt < 2; mt++)
#pragma unroll
                    for (int n2 = 0; n2 < 2; n2++)
                        mma16816(acc[mt][i * 2 + n2], Ah[mt], Bl + n2 * 2);
#pragma unroll
                for (int mt = 0; mt < 2; mt++)
#pragma unroll
                    for (int n2 = 0; n2 < 2; n2++)
                        mma16816(acc[mt][i * 2 + n2], Al[mt], Bh + n2 * 2);
            }
        }
    }

    // ---- epilogue: fragments -> SMEM Y, then coalesced X dot ----
    __syncthreads();          // all MMA/ldmatrix done; buffers now dead
    float* Ysm = (float*)smem;
#pragma unroll
    for (int mt = 0; mt < 2; mt++)
#pragma unroll
        for (int i = 0; i < 4; i++)
#pragma unroll
            for (int n2 = 0; n2 < 2; n2++)
#pragma unroll
                for (int half = 0; half < 2; half++) {
                    int row = wr * 32 + mt * 16 + (lane >> 2) + half * 8;
                    int col = i * 64 + wc * 16 + n2 * 8 + (lane & 3) * 2;
                    float2 v = make_float2(acc[mt][i * 2 + n2][half * 2 + 0],
                                           acc[mt][i * 2 + n2][half * 2 + 1]);
                    *(float2*)&Ysm[row * YSTRIDE + col] = v;
                }
    __syncthreads();

    // pass 2: warp w owns rows w*8 .. w*8+8; coalesced X read
#pragma unroll
    for (int i = 0; i < 8; i++) {
        int rloc = w * 8 + i;
        int rg   = row0 + rloc;
        float q = 0.f, nn = 0.f;
        if (rg < n_atoms) {
#pragma unroll
            for (int k = 0; k < 4; k++) {
                float2 xv = *(const float2*)&X[(size_t)rg * D_FEAT + k * 64 + lane * 2];
                float2 yv = *(const float2*)&Ysm[rloc * YSTRIDE + k * 64 + lane * 2];
                q  = fmaf(xv.x, yv.x, q);
                q  = fmaf(xv.y, yv.y, q);
                nn = fmaf(xv.x, xv.x, nn);
                nn = fmaf(xv.y, xv.y, nn);
            }
        }
#pragma unroll
        for (int off = 16; off > 0; off >>= 1) {
            q  += __shfl_xor_sync(0xFFFFFFFFu, q, off);
            nn += __shfl_xor_sync(0xFFFFFFFFu, nn, off);
        }
        if (lane == 0 && rg < n_atoms)
            atomicAdd(&out[rowseg[rg]], 2.0f * q / nn);
    }
}

// ---- launch --------------------------------------------------------------------
extern "C" void kernel_launch(void* const* d_in, const int* in_sizes, int n_in,
                              void* d_out, int out_size) {
    const float* X      = (const float*)d_in[0];
    const float* S      = (const float*)d_in[1];
    const float* W      = (const float*)d_in[2];
    const int*   rowseg = (const int*)d_in[3];
    const int*   colseg = (const int*)d_in[4];
    float* out = (float*)d_out;

    int n_atoms   = in_sizes[0] / D_FEAT;
    int n_support = in_sizes[1] / D_FEAT;
    int n_struct  = out_size;

    cudaFuncSetAttribute(k_quad_mma, cudaFuncAttributeMaxDynamicSharedMemorySize,
                         SMQ_TOTAL);
    cudaFuncSetAttribute(k_build_mma, cudaFuncAttributeMaxDynamicSharedMemorySize,
                         SMB_TOTAL);

    k_build_mma<<<3 * NSPL, 512, SMB_TOTAL>>>(S, W, colseg, n_support);
    k_convM<<<D_FEAT * D_FEAT / 256, 256>>>(out, n_struct);
    int gQ = (n_atoms + QM - 1) / QM;
    k_quad_mma<<<gQ, 512, SMQ_TOTAL>>>(X, rowseg, out, n_atoms);
}

// round 15
// speedup vs baseline: 1.1170x; 1.0030x over previous
#include <cuda_runtime.h>
#include <cuda_bf16.h>
#include <cstdint>

// ============================================================================
// FullGap: out[s] = sum_{i in s} (p_i^T M p_i)/(p_i.p_i),
//          M = sum_j w[colseg[j]] s_j s_j^T  (256x256 symmetric)
// x^T M x = 2 x^T U x,  U = strict-upper(M) + diag(M)/2.
// R15: R14 + (a) convM fused into build tail via monotone-counter grid barrier
//      (129 CTAs co-resident, no deadlock), (b) quad pass-2 reads X chunks 2,3
//      from resident SMEM stages (exact same bits; warps 0,1 keep global for
//      chunk 2 due to the 4KB Ysm/QAF(0) overlap).
// ============================================================================

#define D_FEAT 256
#define QM 128
#define NSPL 43    // splits per tile; 43*192 = 8256 >= 8192

__device__ float g_bpart[3 * NSPL][16384];                      // 8.4 MB partials
__device__ __align__(16) __nv_bfloat16 g_Uhi[D_FEAT * D_FEAT];  // [n][a]
__device__ __align__(16) __nv_bfloat16 g_Ulo[D_FEAT * D_FEAT];
__device__ int g_ctr;                                           // monotone barrier

// ---------------- helpers ----------------------------------------------------
__device__ __forceinline__ uint32_t smem_u32(const void* p) {
    uint32_t a;
    asm("{ .reg .u64 t; cvta.to.shared.u64 t, %1; cvt.u32.u64 %0, t; }"
        : "=r"(a) : "l"(p));
    return a;
}
__device__ __forceinline__ uint32_t sw_off(uint32_t off) {
    return off ^ ((off >> 3) & 0x70);
}
__device__ __forceinline__ void cpa16(uint32_t dst, const void* src) {
    asm volatile("cp.async.cg.shared.global [%0], [%1], 16;"
                 :: "r"(dst), "l"(__cvta_generic_to_global(src)) : "memory");
}
#define CP_COMMIT() asm volatile("cp.async.commit_group;" ::: "memory")
#define CP_WAIT(n)  asm volatile("cp.async.wait_group %0;" :: "n"(n) : "memory")

// non-trans A: smem[m][k]
__device__ __forceinline__ void ldsmA(uint32_t base, int rb, int kk, int lane,
                                      uint32_t* a) {
    int g = lane >> 3, r = lane & 7;
    int row = rb + r + (g & 1) * 8;
    int col = kk + (g >> 1) * 8;
    uint32_t addr = base + sw_off((uint32_t)(row * 128 + col * 2));
    asm volatile("ldmatrix.sync.aligned.m8n8.x4.shared.b16 {%0,%1,%2,%3}, [%4];"
                 : "=r"(a[0]), "=r"(a[1]), "=r"(a[2]), "=r"(a[3]) : "r"(addr));
}
// non-trans B: smem[n][k]
__device__ __forceinline__ void ldsmB(uint32_t base, int nb, int kk, int lane,
                                      uint32_t* b) {
    int g = lane >> 3, r = lane & 7;
    int row = nb + r + (g >> 1) * 8;
    int col = kk + (g & 1) * 8;
    uint32_t addr = base + sw_off((uint32_t)(row * 128 + col * 2));
    asm volatile("ldmatrix.sync.aligned.m8n8.x4.shared.b16 {%0,%1,%2,%3}, [%4];"
                 : "=r"(b[0]), "=r"(b[1]), "=r"(b[2]), "=r"(b[3]) : "r"(addr));
}
// trans A: smem[j][m], panels of 64 rows x 64 cols (8 KB)
__device__ __forceinline__ void ldsmT_A(uint32_t base, int ab, int kk, int lane,
                                        uint32_t* a) {
    int g = lane >> 3, r = lane & 7;
    int row = kk + r + (g >> 1) * 8;
    int col = ab + (g & 1) * 8;
    uint32_t addr = base + (uint32_t)(col >> 6) * 8192 +
                    sw_off((uint32_t)(row * 128 + (col & 63) * 2));
    asm volatile("ldmatrix.sync.aligned.m8n8.x4.trans.shared.b16 {%0,%1,%2,%3}, [%4];"
                 : "=r"(a[0]), "=r"(a[1]), "=r"(a[2]), "=r"(a[3]) : "r"(addr));
}
// trans B: smem[j][n]
__device__ __forceinline__ void ldsmT_B(uint32_t base, int nb, int kk, int lane,
                                        uint32_t* b) {
    int g = lane >> 3, r = lane & 7;
    int row = kk + r + (g & 1) * 8;
    int col = nb + (g >> 1) * 8;
    uint32_t addr = base + (uint32_t)(col >> 6) * 8192 +
                    sw_off((uint32_t)(row * 128 + (col & 63) * 2));
    asm volatile("ldmatrix.sync.aligned.m8n8.x4.trans.shared.b16 {%0,%1,%2,%3}, [%4];"
                 : "=r"(b[0]), "=r"(b[1]), "=r"(b[2]), "=r"(b[3]) : "r"(addr));
}
__device__ __forceinline__ void mma16816(float* c, const uint32_t* a,
                                         const uint32_t* b) {
    asm volatile(
        "mma.sync.aligned.m16n8k16.row.col.f32.bf16.bf16.f32 "
        "{%0,%1,%2,%3}, {%4,%5,%6,%7}, {%8,%9}, {%0,%1,%2,%3};"
        : "+f"(c[0]), "+f"(c[1]), "+f"(c[2]), "+f"(c[3])
        : "r"(a[0]), "r"(a[1]), "r"(a[2]), "r"(a[3]), "r"(b[0]), "r"(b[1]));
}
__device__ __forceinline__ void bsplit(float x, float y, uint32_t& hi, uint32_t& lo) {
    float hx = __bfloat162float(__float2bfloat16(x));
    float hy = __bfloat162float(__float2bfloat16(y));
    __nv_bfloat162 h = __floats2bfloat162_rn(hx, hy);
    __nv_bfloat162 l = __floats2bfloat162_rn(x - hx, y - hy);
    hi = *(uint32_t*)&h;
    lo = *(uint32_t*)&l;
}

// ---- build: M[a,b] = sum_j S[j][a] * w_j S[j][b] + fused convM tail -----------
#define FB_A(s) ((uint32_t)(s) * 32768u)
#define FB_B(s) (65536u + (uint32_t)(s) * 32768u)
#define BAH 131072u
#define BAL 147456u
#define BBH 163840u
#define BBL 180224u
#define BWO 196608u
#define SMB_TOTAL 197632

__device__ __forceinline__ void b_issue(char* smem, uint32_t sbase,
                                        const float* S, int stage, int jb,
                                        int a0, int b0, bool same,
                                        int n_support, int t) {
#pragma unroll
    for (int p = 0; p < 4; p++) {
        int g = t + p * 512;          // 2048 granules = 64 j x 32 float4
        int jl = g >> 5, cq = g & 31;
        int jg = jb + jl;
        uint32_t dst = FB_A(stage) + (uint32_t)(jl * 512 + cq * 16);
        if (jg < n_support)
            cpa16(sbase + dst, &S[(size_t)jg * D_FEAT + a0 + cq * 4]);
        else
            *(uint4*)(smem + dst) = make_uint4(0, 0, 0, 0);
    }
    if (!same) {
#pragma unroll
        for (int p = 0; p < 4; p++) {
            int g = t + p * 512;
            int jl = g >> 5, cq = g & 31;
            int jg = jb + jl;
            uint32_t dst = FB_B(stage) + (uint32_t)(jl * 512 + cq * 16);
            if (jg < n_support)
                cpa16(sbase + dst, &S[(size_t)jg * D_FEAT + b0 + cq * 4]);
            else
                *(uint4*)(smem + dst) = make_uint4(0, 0, 0, 0);
        }
    }
}

__global__ void __launch_bounds__(512, 1)
k_build_mma(const float* __restrict__ S, const float* __restrict__ W,
            const int* __restrict__ colseg, int n_support,
            float* __restrict__ out, int n_struct) {
    extern __shared__ char smem[];
    const uint32_t sbase = smem_u32(smem);
    float* wsm = (float*)(smem + BWO);
    const int t    = threadIdx.x;
    const int lane = t & 31;
    const int w    = t >> 5;
    const int wr   = w & 3;
    const int wc   = w >> 2;

    const int tile  = blockIdx.x / NSPL;
    const int split = blockIdx.x % NSPL;
    const int a0 = (tile == 2) ? 128 : 0;
    const int b0 = (tile == 0) ? 0 : 128;
    const bool same = (tile != 1);       // diagonal tiles share the slab
    const int jorg = split * 192;

    if (t < 192) {
        int jg = jorg + t;
        wsm[t] = (jg < n_support) ? W[colseg[jg]] : 0.f;
    }

    b_issue(smem, sbase, S, 0, jorg, a0, b0, same, n_support, t);
    CP_COMMIT();

    float acc[2][4][4];
#pragma unroll
    for (int mt = 0; mt < 2; mt++)
#pragma unroll
        for (int nt = 0; nt < 4; nt++)
#pragma unroll
            for (int e = 0; e < 4; e++) acc[mt][nt][e] = 0.f;

#pragma unroll 1
    for (int c = 0; c < 3; c++) {
        const int st = c & 1;
        if (c < 2) {
            b_issue(smem, sbase, S, 1 - st, jorg + (c + 1) * 64, a0, b0, same,
                    n_support, t);
            CP_COMMIT();
            CP_WAIT(1);
        } else {
            CP_WAIT(0);
        }
        __syncthreads();

        // convert A: fp32 -> bf16 hi/lo trans panels
#pragma unroll
        for (int p = 0; p < 4; p++) {
            int g = t + p * 512;
            int jl = g >> 5, cq = g & 31;
            float4 v = *(const float4*)(smem + FB_A(st) + jl * 512 + cq * 16);
            uint32_t h0, l0, h1, l1;
            bsplit(v.x, v.y, h0, l0);
            bsplit(v.z, v.w, h1, l1);
            uint32_t off = (uint32_t)(cq >> 4) * 8192 +
                           sw_off((uint32_t)(jl * 128 + (cq & 15) * 8));
            *(uint2*)(smem + BAH + off) = make_uint2(h0, h1);
            *(uint2*)(smem + BAL + off) = make_uint2(l0, l1);
        }
        // convert B: w_j * fp32 -> bf16 hi/lo (same slab for diag tiles)
#pragma unroll
        for (int p = 0; p < 4; p++) {
            int g = t + p * 512;
            int jl = g >> 5, cq = g & 31;
            uint32_t src = (same ? FB_A(st) : FB_B(st)) +
                           (uint32_t)(jl * 512 + cq * 16);
            float4 v = *(const float4*)(smem + src);
            float wj = wsm[c * 64 + jl];
            uint32_t h0, l0, h1, l1;
            bsplit(wj * v.x, wj * v.y, h0, l0);
            bsplit(wj * v.z, wj * v.w, h1, l1);
            uint32_t off = (uint32_t)(cq >> 4) * 8192 +
                           sw_off((uint32_t)(jl * 128 + (cq & 15) * 8));
            *(uint2*)(smem + BBH + off) = make_uint2(h0, h1);
            *(uint2*)(smem + BBL + off) = make_uint2(l0, l1);
        }
        __syncthreads();

#pragma unroll
        for (int ks = 0; ks < 4; ks++) {
            const int kk = ks * 16;
            uint32_t Ah[2][4], Al[2][4], Bh[2][4], Bl[2][4];
            ldsmT_A(sbase + BAH, wr * 32 + 0,  kk, lane, Ah[0]);
            ldsmT_A(sbase + BAH, wr * 32 + 16, kk, lane, Ah[1]);
            ldsmT_A(sbase + BAL, wr * 32 + 0,  kk, lane, Al[0]);
            ldsmT_A(sbase + BAL, wr * 32 + 16, kk, lane, Al[1]);
            ldsmT_B(sbase + BBH, wc * 32 + 0,  kk, lane, Bh[0]);
            ldsmT_B(sbase + BBH, wc * 32 + 16, kk, lane, Bh[1]);
            ldsmT_B(sbase + BBL, wc * 32 + 0,  kk, lane, Bl[0]);
            ldsmT_B(sbase + BBL, wc * 32 + 16, kk, lane, Bl[1]);
#pragma unroll
            for (int np = 0; np < 2; np++)
#pragma unroll
                for (int mt = 0; mt < 2; mt++)
#pragma unroll
                    for (int n2 = 0; n2 < 2; n2++)
                        mma16816(acc[mt][np * 2 + n2], Ah[mt], Bh[np] + n2 * 2);
#pragma unroll
            for (int np = 0; np < 2; np++)
#pragma unroll
                for (int mt = 0; mt < 2; mt++)
#pragma unroll
                    for (int n2 = 0; n2 < 2; n2++)
                        mma16816(acc[mt][np * 2 + n2], Ah[mt], Bl[np] + n2 * 2);
#pragma unroll
            for (int np = 0; np < 2; np++)
#pragma unroll
                for (int mt = 0; mt < 2; mt++)
#pragma unroll
                    for (int n2 = 0; n2 < 2; n2++)
                        mma16816(acc[mt][np * 2 + n2], Al[mt], Bh[np] + n2 * 2);
        }
    }

    __syncthreads();
    float* stg = (float*)smem;
#pragma unroll
    for (int mt = 0; mt < 2; mt++)
#pragma unroll
        for (int nt = 0; nt < 4; nt++)
#pragma unroll
            for (int e = 0; e < 4; e++) {
                int a = wr * 32 + mt * 16 + (lane >> 2) + (e >> 1) * 8;
                int b = wc * 32 + nt * 8 + (lane & 3) * 2 + (e & 1);
                stg[b * 128 + a] = acc[mt][nt][e];
            }
    __syncthreads();
    float* dst = g_bpart[blockIdx.x];
#pragma unroll
    for (int i = 0; i < 32; i++)
        dst[i * 512 + t] = stg[i * 512 + t];

    // ---- grid barrier (all 129 CTAs co-resident: 1 CTA/SM, grid < #SM) ----
    __threadfence();          // publish this thread's partial stores
    __syncthreads();          // all threads of CTA published before t0 arrives
    if (t == 0) {
        int old = atomicAdd(&g_ctr, 1);
        int target = old - (old % (int)gridDim.x) + (int)gridDim.x;
        while (atomicAdd(&g_ctr, 0) < target) { }
    }
    __syncthreads();
    __threadfence();          // acquire: order subsequent loads

    // ---- fused convM: reduce partials -> U bf16 hi/lo, zero out ----
    int i = blockIdx.x * 512 + t;           // 129*512 = 66048 >= 65536
    if (i < D_FEAT * D_FEAT) {
        int a = i & 255, n = i >> 8;
        float v = 0.f;
        if (a <= n) {
            int tl = (n < 128) ? 0 : ((a < 128) ? 1 : 2);
            int idx = (n & 127) * 128 + (a & 127);
            const float* bp = g_bpart[tl * NSPL];
#pragma unroll
            for (int s = 0; s < NSPL; s++) v += bp[(size_t)s * 16384 + idx];
            if (a == n) v *= 0.5f;
        }
        __nv_bfloat16 h = __float2bfloat16(v);
        g_Uhi[i] = h;
        g_Ulo[i] = __float2bfloat16(v - __bfloat162float(h));
    }
    if (i < n_struct) out[i] = 0.f;
}

// ---- quad kernel: striped cols + diag skip, SMEM-Y epilogue, SMEM-X pass2 -----
#define QB(s)   ((uint32_t)(s) * 65536u)
#define QBL(s)  ((uint32_t)(s) * 65536u + 32768u)
#define QAF(s)  (131072u + (uint32_t)(s) * 32768u)
#define QAH     196608u
#define QAL     212992u
#define SMQ_TOTAL 229376
#define YSTRIDE 264   // floats

__device__ __forceinline__ void q_issue(char* smem, uint32_t sbase,
                                        const float* X, int stage, int c,
                                        int row0, int n_atoms, int t) {
    const int k0 = c * 64;
#pragma unroll
    for (int p = 0; p < 4; p++) {
        int g = t + p * 512;
        int row = g >> 4, q16 = g & 15;
        uint32_t dst = QAF(stage) + (uint32_t)(row * 256 + q16 * 16);
        if (row0 + row < n_atoms) {
            cpa16(sbase + dst, &X[(size_t)(row0 + row) * D_FEAT + k0 + q16 * 4]);
        } else {
            *(uint4*)(smem + dst) = make_uint4(0, 0, 0, 0);
        }
    }
#pragma unroll
    for (int p = 0; p < 4; p++) {
        int g = t + p * 512;
        int row = g >> 3, kq = g & 7;
        if (row >= c * 64) {
            uint32_t so = sw_off((uint32_t)(row * 128 + kq * 16));
            size_t src = (size_t)row * D_FEAT + k0 + kq * 8;
            cpa16(sbase + QB(stage) + so, &g_Uhi[src]);
            cpa16(sbase + QBL(stage) + so, &g_Ulo[src]);
        }
    }
}

__global__ void __launch_bounds__(512, 1)
k_quad_mma(const float* __restrict__ X, const int* __restrict__ rowseg,
           float* __restrict__ out, int n_atoms) {
    extern __shared__ char smem[];
    const uint32_t sbase = smem_u32(smem);
    const int t    = threadIdx.x;
    const int lane = t & 31;
    const int w    = t >> 5;
    const int wr   = w & 3;
    const int wc   = w >> 2;
    const int row0 = blockIdx.x * QM;

    float acc[2][8][4];
#pragma unroll
    for (int mt = 0; mt < 2; mt++)
#pragma unroll
        for (int nt = 0; nt < 8; nt++)
#pragma unroll
            for (int e = 0; e < 4; e++) acc[mt][nt][e] = 0.f;

    q_issue(smem, sbase, X, 0, 0, row0, n_atoms, t);
    CP_COMMIT();

#pragma unroll
    for (int c = 0; c < 4; c++) {
        const int st = c & 1;
        CP_WAIT(0);
        __syncthreads();
        if (c < 3) {
            q_issue(smem, sbase, X, 1 - st, c + 1, row0, n_atoms, t);
            CP_COMMIT();
        }
        // convert A fp32 stage -> bf16 hi/lo (SW128)
#pragma unroll
        for (int p = 0; p < 4; p++) {
            int g = t + p * 512;
            int row = g >> 4, kq = g & 15;
            float4 v = *(const float4*)(smem + QAF(st) + row * 256 + kq * 16);
            uint32_t h0, l0, h1, l1;
            bsplit(v.x, v.y, h0, l0);
            bsplit(v.z, v.w, h1, l1);
            uint32_t so = sw_off((uint32_t)(row * 128 + kq * 8));
            *(uint2*)(smem + QAH + so) = make_uint2(h0, h1);
            *(uint2*)(smem + QAL + so) = make_uint2(l0, l1);
        }
        __syncthreads();

#pragma unroll
        for (int ks = 0; ks < 4; ks++) {
            const int kk = ks * 16;
            uint32_t Ah[2][4], Al[2][4];
            ldsmA(sbase + QAH, wr * 32 + 0,  kk, lane, Ah[0]);
            ldsmA(sbase + QAH, wr * 32 + 16, kk, lane, Ah[1]);
            ldsmA(sbase + QAL, wr * 32 + 0,  kk, lane, Al[0]);
            ldsmA(sbase + QAL, wr * 32 + 16, kk, lane, Al[1]);
#pragma unroll
            for (int i = 0; i < 4; i++) {
                if (i < c) continue;              // stripe fully below diagonal
                if (i == c && ks > wc) continue;  // diagonal block: U == 0 exactly
                uint32_t Bh[4], Bl[4];
                ldsmB(sbase + QB(st),  i * 64 + wc * 16, kk, lane, Bh);
                ldsmB(sbase + QBL(st), i * 64 + wc * 16, kk, lane, Bl);
#pragma unroll
                for (int mt = 0; mt < 2; mt++)
#pragma unroll
                    for (int n2 = 0; n2 < 2; n2++)
                        mma16816(acc[mt][i * 2 + n2], Ah[mt], Bh + n2 * 2);
#pragma unroll
                for (int mt = 0; mt < 2; mt++)
#pragma unroll
                    for (int n2 = 0; n2 < 2; n2++)
                        mma16816(acc[mt][i * 2 + n2], Ah[mt], Bl + n2 * 2);
#pragma unroll
                for (int mt = 0; mt < 2; mt++)
#pragma unroll
                    for (int n2 = 0; n2 < 2; n2++)
                        mma16816(acc[mt][i * 2 + n2], Al[mt], Bh + n2 * 2);
            }
        }
    }

    // ---- epilogue: fragments -> SMEM Y, then X dot (mixed SMEM/global X) ----
    // Stage residency after mainloop: QAF(0) = X chunk 2, QAF(1) = X chunk 3.
    // Ysm spans [0, 135168) and clobbers QAF(0) bytes [0,4096) = stage rows
    // 0..15 = warps 0,1 -> those warps read chunk 2 from global instead.
    __syncthreads();          // all MMA/ldmatrix done; buffers now dead
    float* Ysm = (float*)smem;
#pragma unroll
    for (int mt = 0; mt < 2; mt++)
#pragma unroll
        for (int i = 0; i < 4; i++)
#pragma unroll
            for (int n2 = 0; n2 < 2; n2++)
#pragma unroll
                for (int half = 0; half < 2; half++) {
                    int row = wr * 32 + mt * 16 + (lane >> 2) + half * 8;
                    int col = i * 64 + wc * 16 + n2 * 8 + (lane & 3) * 2;
                    float2 v = make_float2(acc[mt][i * 2 + n2][half * 2 + 0],
                                           acc[mt][i * 2 + n2][half * 2 + 1]);
                    *(float2*)&Ysm[row * YSTRIDE + col] = v;
                }
    __syncthreads();

    // pass 2: warp w owns rows w*8 .. w*8+8
#pragma unroll
    for (int i = 0; i < 8; i++) {
        int rloc = w * 8 + i;
        int rg   = row0 + rloc;
        float q = 0.f, nn = 0.f;
        if (rg < n_atoms) {
#pragma unroll
            for (int k = 0; k < 4; k++) {
                float2 xv;
                if (k < 2) {
                    xv = *(const float2*)&X[(size_t)rg * D_FEAT + k * 64 + lane * 2];
                } else if (k == 2) {
                    if (w < 2)
                        xv = *(const float2*)&X[(size_t)rg * D_FEAT + 128 + lane * 2];
                    else
                        xv = *(const float2*)(smem + QAF(0) +
                                              (uint32_t)(rloc * 256 + lane * 8));
                } else {
                    xv = *(const float2*)(smem + QAF(1) +
                                          (uint32_t)(rloc * 256 + lane * 8));
                }
                float2 yv = *(const float2*)&Ysm[rloc * YSTRIDE + k * 64 + lane * 2];
                q  = fmaf(xv.x, yv.x, q);
                q  = fmaf(xv.y, yv.y, q);
                nn = fmaf(xv.x, xv.x, nn);
                nn = fmaf(xv.y, xv.y, nn);
            }
        }
#pragma unroll
        for (int off = 16; off > 0; off >>= 1) {
            q  += __shfl_xor_sync(0xFFFFFFFFu, q, off);
            nn += __shfl_xor_sync(0xFFFFFFFFu, nn, off);
        }
        if (lane == 0 && rg < n_atoms)
            atomicAdd(&out[rowseg[rg]], 2.0f * q / nn);
    }
}

// ---- launch --------------------------------------------------------------------
extern "C" void kernel_launch(void* const* d_in, const int* in_sizes, int n_in,
                              void* d_out, int out_size) {
    const float* X      = (const float*)d_in[0];
    const float* S      = (const float*)d_in[1];
    const float* W      = (const float*)d_in[2];
    const int*   rowseg = (const int*)d_in[3];
    const int*   colseg = (const int*)d_in[4];
    float* out = (float*)d_out;

    int n_atoms   = in_sizes[0] / D_FEAT;
    int n_support = in_sizes[1] / D_FEAT;
    int n_struct  = out_size;

    cudaFuncSetAttribute(k_quad_mma, cudaFuncAttributeMaxDynamicSharedMemorySize,
                         SMQ_TOTAL);
    cudaFuncSetAttribute(k_build_mma, cudaFuncAttributeMaxDynamicSharedMemorySize,
                         SMB_TOTAL);

    k_build_mma<<<3 * NSPL, 512, SMB_TOTAL>>>(S, W, colseg, n_support,
                                              out, n_struct);
    int gQ = (n_atoms + QM - 1) / QM;
    k_quad_mma<<<gQ, 512, SMQ_TOTAL>>>(X, rowseg, out, n_atoms);
}